// round 2
// baseline (speedup 1.0000x reference)
#include <cuda_runtime.h>

#define HF 64
#define MAX_NODES 100000

// Scratch tables: A[n] = h[n]@W1[:64] + b1,  B[n] = h[n]@W1[64:]
__device__ float g_A[MAX_NODES * HF];
__device__ float g_B[MAX_NODES * HF];

// ---------------- precompute: per-node GEMM ----------------
// block: 256 threads, 64 nodes. thread: 8 nodes x 2 output feats (A and B).
__global__ __launch_bounds__(256)
void precompute_kernel(const float* __restrict__ h,
                       const float* __restrict__ W1,
                       const float* __restrict__ b1,
                       int n_nodes)
{
    __shared__ float h_sm[64 * HF];      // 16 KB
    __shared__ float w1s_sm[HF * HF];    // 16 KB
    __shared__ float w1d_sm[HF * HF];    // 16 KB

    const int tid   = threadIdx.x;
    const int node0 = blockIdx.x * 64;

    // Stage W1 (both halves) into smem
    const float4* W14 = (const float4*)W1;
    float4* ws4 = (float4*)w1s_sm;
    float4* wd4 = (float4*)w1d_sm;
    #pragma unroll
    for (int i = tid; i < HF * HF / 4; i += 256) {
        ws4[i] = W14[i];
        wd4[i] = W14[i + HF * HF / 4];
    }
    // Stage 64 node rows of h
    const float4* h4 = (const float4*)h;
    float4* hs4 = (float4*)h_sm;
    #pragma unroll
    for (int i = tid; i < 64 * HF / 4; i += 256) {
        int node = node0 + (i >> 4);
        hs4[i] = (node < n_nodes) ? h4[(size_t)node * (HF / 4) + (i & 15)]
                                  : make_float4(0.f, 0.f, 0.f, 0.f);
    }
    __syncthreads();

    const int jg = tid & 31;   // feature pair index: j0 = 2*jg  (covers 64 feats)
    const int j0 = jg * 2;
    const int ng = tid >> 5;   // warp id -> node group of 8
    const int nb = ng * 8;

    float aA[8][2], aB[8][2];
    #pragma unroll
    for (int ni = 0; ni < 8; ++ni) {
        aA[ni][0] = aA[ni][1] = 0.f;
        aB[ni][0] = aB[ni][1] = 0.f;
    }

    for (int k = 0; k < HF; k += 4) {
        // h values: all lanes of a warp read the SAME address -> smem broadcast
        float4 hv[8];
        #pragma unroll
        for (int ni = 0; ni < 8; ++ni)
            hv[ni] = *(const float4*)&h_sm[(nb + ni) * HF + k];
        #pragma unroll
        for (int kk = 0; kk < 4; ++kk) {
            float2 ws = *(const float2*)&w1s_sm[(k + kk) * HF + j0];
            float2 wd = *(const float2*)&w1d_sm[(k + kk) * HF + j0];
            #pragma unroll
            for (int ni = 0; ni < 8; ++ni) {
                float hvv = (kk == 0) ? hv[ni].x : (kk == 1) ? hv[ni].y
                          : (kk == 2) ? hv[ni].z : hv[ni].w;
                aA[ni][0] = fmaf(hvv, ws.x, aA[ni][0]);
                aA[ni][1] = fmaf(hvv, ws.y, aA[ni][1]);
                aB[ni][0] = fmaf(hvv, wd.x, aB[ni][0]);
                aB[ni][1] = fmaf(hvv, wd.y, aB[ni][1]);
            }
        }
    }

    float2 bb = *(const float2*)&b1[j0];
    #pragma unroll
    for (int ni = 0; ni < 8; ++ni) {
        int node = node0 + nb + ni;
        if (node < n_nodes) {
            float2 va = make_float2(aA[ni][0] + bb.x, aA[ni][1] + bb.y);
            float2 vb = make_float2(aB[ni][0], aB[ni][1]);
            *(float2*)&g_A[(size_t)node * HF + j0] = va;
            *(float2*)&g_B[(size_t)node * HF + j0] = vb;
        }
    }
}

// ---------------- edge scoring: L2-resident gather ----------------
// 16 lanes per edge (float4/lane), 2 edges per warp.
__global__ __launch_bounds__(256)
void edge_kernel(const int* __restrict__ src,
                 const int* __restrict__ dst,
                 const float* __restrict__ W2,
                 const float* __restrict__ b2,
                 float* __restrict__ out, int n_edges)
{
    const int lane = threadIdx.x & 31;
    const int half = lane >> 4;   // which edge of the pair
    const int l    = lane & 15;   // feature group (4 floats)

    int e = (blockIdx.x * 8 + (threadIdx.x >> 5)) * 2 + half;
    bool valid = (e < n_edges);
    int ec = valid ? e : (n_edges - 1);

    int s = src[ec];
    int d = dst[ec];

    const float4* A4 = (const float4*)g_A;
    const float4* B4 = (const float4*)g_B;
    float4 a = A4[s * 16 + l];
    float4 b = B4[d * 16 + l];
    float4 w = ((const float4*)W2)[l];

    float v0 = fmaxf(a.x + b.x, 0.f);
    float v1 = fmaxf(a.y + b.y, 0.f);
    float v2 = fmaxf(a.z + b.z, 0.f);
    float v3 = fmaxf(a.w + b.w, 0.f);

    float acc = fmaf(v0, w.x, fmaf(v1, w.y, fmaf(v2, w.z, v3 * w.w)));

    // reduce within the 16-lane half (xor 8/4/2/1 never crosses halves)
    acc += __shfl_xor_sync(0xffffffffu, acc, 8);
    acc += __shfl_xor_sync(0xffffffffu, acc, 4);
    acc += __shfl_xor_sync(0xffffffffu, acc, 2);
    acc += __shfl_xor_sync(0xffffffffu, acc, 1);

    if (valid && l == 0) out[e] = acc + b2[0];
}

extern "C" void kernel_launch(void* const* d_in, const int* in_sizes, int n_in,
                              void* d_out, int out_size)
{
    const float* h   = (const float*)d_in[0];
    const int*   src = (const int*)d_in[1];
    const int*   dst = (const int*)d_in[2];
    const float* W1  = (const float*)d_in[3];
    const float* b1  = (const float*)d_in[4];
    const float* W2  = (const float*)d_in[5];
    const float* b2  = (const float*)d_in[6];
    float* out = (float*)d_out;

    int n_nodes = in_sizes[0] / HF;
    int n_edges = in_sizes[1];

    precompute_kernel<<<(n_nodes + 63) / 64, 256>>>(h, W1, b1, n_nodes);
    edge_kernel<<<(n_edges + 15) / 16, 256>>>(src, dst, W2, b2, out, n_edges);
}

// round 3
// speedup vs baseline: 2.1423x; 2.1423x over previous
#include <cuda_runtime.h>
#include <cuda_fp16.h>

#define HF 64
#define MAX_NODES 100000

// Scratch tables in fp16: A[n] = h[n]@W1[:64] + b1,  B[n] = h[n]@W1[64:]
__device__ __half g_A[MAX_NODES * HF];
__device__ __half g_B[MAX_NODES * HF];

// ---------------- precompute: per-node GEMM ----------------
// block: 256 threads, 64 nodes. thread: 8 nodes x 2 output feats (A and B).
__global__ __launch_bounds__(256)
void precompute_kernel(const float* __restrict__ h,
                       const float* __restrict__ W1,
                       const float* __restrict__ b1,
                       int n_nodes)
{
    __shared__ float h_sm[64 * HF];      // 16 KB
    __shared__ float w1s_sm[HF * HF];    // 16 KB
    __shared__ float w1d_sm[HF * HF];    // 16 KB

    const int tid   = threadIdx.x;
    const int node0 = blockIdx.x * 64;

    // Stage W1 (both halves) into smem
    const float4* W14 = (const float4*)W1;
    float4* ws4 = (float4*)w1s_sm;
    float4* wd4 = (float4*)w1d_sm;
    #pragma unroll
    for (int i = tid; i < HF * HF / 4; i += 256) {
        ws4[i] = W14[i];
        wd4[i] = W14[i + HF * HF / 4];
    }
    // Stage 64 node rows of h
    const float4* h4 = (const float4*)h;
    float4* hs4 = (float4*)h_sm;
    #pragma unroll
    for (int i = tid; i < 64 * HF / 4; i += 256) {
        int node = node0 + (i >> 4);
        hs4[i] = (node < n_nodes) ? h4[(size_t)node * (HF / 4) + (i & 15)]
                                  : make_float4(0.f, 0.f, 0.f, 0.f);
    }
    __syncthreads();

    const int jg = tid & 31;   // feature pair index: j0 = 2*jg  (covers 64 feats)
    const int j0 = jg * 2;
    const int ng = tid >> 5;   // warp id -> node group of 8
    const int nb = ng * 8;

    float aA[8][2], aB[8][2];
    #pragma unroll
    for (int ni = 0; ni < 8; ++ni) {
        aA[ni][0] = aA[ni][1] = 0.f;
        aB[ni][0] = aB[ni][1] = 0.f;
    }

    for (int k = 0; k < HF; k += 4) {
        // h values: all lanes of a warp read the SAME address -> smem broadcast
        float4 hv[8];
        #pragma unroll
        for (int ni = 0; ni < 8; ++ni)
            hv[ni] = *(const float4*)&h_sm[(nb + ni) * HF + k];
        #pragma unroll
        for (int kk = 0; kk < 4; ++kk) {
            float2 ws = *(const float2*)&w1s_sm[(k + kk) * HF + j0];
            float2 wd = *(const float2*)&w1d_sm[(k + kk) * HF + j0];
            #pragma unroll
            for (int ni = 0; ni < 8; ++ni) {
                float hvv = (kk == 0) ? hv[ni].x : (kk == 1) ? hv[ni].y
                          : (kk == 2) ? hv[ni].z : hv[ni].w;
                aA[ni][0] = fmaf(hvv, ws.x, aA[ni][0]);
                aA[ni][1] = fmaf(hvv, ws.y, aA[ni][1]);
                aB[ni][0] = fmaf(hvv, wd.x, aB[ni][0]);
                aB[ni][1] = fmaf(hvv, wd.y, aB[ni][1]);
            }
        }
    }

    float2 bb = *(const float2*)&b1[j0];
    #pragma unroll
    for (int ni = 0; ni < 8; ++ni) {
        int node = node0 + nb + ni;
        if (node < n_nodes) {
            *(half2*)&g_A[(size_t)node * HF + j0] =
                __floats2half2_rn(aA[ni][0] + bb.x, aA[ni][1] + bb.y);
            *(half2*)&g_B[(size_t)node * HF + j0] =
                __floats2half2_rn(aB[ni][0], aB[ni][1]);
        }
    }
}

// ---------------- edge scoring: fp16 L2-resident gather ----------------
// 8 lanes per edge (16 bytes = 8 halves per lane), 4 edges per warp.
__global__ __launch_bounds__(256)
void edge_kernel(const int* __restrict__ src,
                 const int* __restrict__ dst,
                 const float* __restrict__ W2,
                 const float* __restrict__ b2,
                 float* __restrict__ out, int n_edges)
{
    const int lane = threadIdx.x & 31;
    const int sub  = lane >> 3;   // edge within warp (0..3)
    const int l    = lane & 7;    // feature group (8 halves)

    int e = (blockIdx.x * 8 + (threadIdx.x >> 5)) * 4 + sub;
    bool valid = (e < n_edges);
    int ec = valid ? e : (n_edges - 1);

    int s = src[ec];
    int d = dst[ec];

    const uint4* A4 = (const uint4*)g_A;   // 8 x uint4 per 64-half row
    const uint4* B4 = (const uint4*)g_B;
    uint4 av = A4[(size_t)s * 8 + l];
    uint4 bv = B4[(size_t)d * 8 + l];

    const float4* W24 = (const float4*)W2;
    float4 w0 = W24[l * 2];
    float4 w1 = W24[l * 2 + 1];

    const __half2* ah = (const __half2*)&av;
    const __half2* bh = (const __half2*)&bv;

    float acc = 0.f;
    float2 a0 = __half22float2(ah[0]), b0 = __half22float2(bh[0]);
    float2 a1 = __half22float2(ah[1]), b1v = __half22float2(bh[1]);
    float2 a2 = __half22float2(ah[2]), b2v = __half22float2(bh[2]);
    float2 a3 = __half22float2(ah[3]), b3 = __half22float2(bh[3]);

    acc = fmaf(fmaxf(a0.x + b0.x, 0.f), w0.x, acc);
    acc = fmaf(fmaxf(a0.y + b0.y, 0.f), w0.y, acc);
    acc = fmaf(fmaxf(a1.x + b1v.x, 0.f), w0.z, acc);
    acc = fmaf(fmaxf(a1.y + b1v.y, 0.f), w0.w, acc);
    acc = fmaf(fmaxf(a2.x + b2v.x, 0.f), w1.x, acc);
    acc = fmaf(fmaxf(a2.y + b2v.y, 0.f), w1.y, acc);
    acc = fmaf(fmaxf(a3.x + b3.x, 0.f), w1.z, acc);
    acc = fmaf(fmaxf(a3.y + b3.y, 0.f), w1.w, acc);

    // reduce within the 8-lane group (xor 4/2/1 never crosses groups)
    acc += __shfl_xor_sync(0xffffffffu, acc, 4);
    acc += __shfl_xor_sync(0xffffffffu, acc, 2);
    acc += __shfl_xor_sync(0xffffffffu, acc, 1);

    if (valid && l == 0) out[e] = acc + b2[0];
}

extern "C" void kernel_launch(void* const* d_in, const int* in_sizes, int n_in,
                              void* d_out, int out_size)
{
    const float* h   = (const float*)d_in[0];
    const int*   src = (const int*)d_in[1];
    const int*   dst = (const int*)d_in[2];
    const float* W1  = (const float*)d_in[3];
    const float* b1  = (const float*)d_in[4];
    const float* W2  = (const float*)d_in[5];
    const float* b2  = (const float*)d_in[6];
    float* out = (float*)d_out;

    int n_nodes = in_sizes[0] / HF;
    int n_edges = in_sizes[1];

    precompute_kernel<<<(n_nodes + 63) / 64, 256>>>(h, W1, b1, n_nodes);
    edge_kernel<<<(n_edges + 31) / 32, 256>>>(src, dst, W2, b2, out, n_edges);
}

// round 4
// speedup vs baseline: 2.2072x; 1.0303x over previous
#include <cuda_runtime.h>
#include <cuda_fp16.h>
#include <mma.h>

using namespace nvcuda;

#define HF 64
#define MAX_NODES 100000

// Scratch tables in fp16: A[n] = h[n]@W1[:64] + b1,  B[n] = h[n]@W1[64:]
__device__ __half g_A[MAX_NODES * HF];
__device__ __half g_B[MAX_NODES * HF];

// ---------------- precompute: tf32 WMMA GEMM ----------------
// Per block: 64 nodes x 128 outputs ([A|B]).  C = h(64x64) @ W'(64x128).
// W'[k][j<64] = W1[k][j] (src half), W'[k][64+j] = W1[64+k][j] (dst half).
// smem: 48KB total; h at [0,4096), W' at [4096,12288) floats.
// After MMA, C (64x128 fp32 = 32KB) overlaps [0,8192).
__global__ __launch_bounds__(256)
void precompute_kernel(const float* __restrict__ h,
                       const float* __restrict__ W1,
                       const float* __restrict__ b1,
                       int n_nodes)
{
    __shared__ float smem[12288];          // 48 KB
    float* h_sm = smem;                    // 64 x 64
    float* w_sm = smem + 4096;             // 64 x 128
    float* c_sm = smem;                    // 64 x 128 (after sync)

    const int tid   = threadIdx.x;
    const int node0 = blockIdx.x * 64;

    // Stage W' : row k = [W1 row k | W1 row 64+k]
    const float4* W14 = (const float4*)W1;
    float4* w4 = (float4*)w_sm;
    #pragma unroll
    for (int i = tid; i < 2048; i += 256) {          // 64 rows x 32 float4
        int k = i >> 5, c = i & 31;
        w4[i] = (c < 16) ? W14[k * 16 + c] : W14[(64 + k) * 16 + (c - 16)];
    }
    // Stage 64 node rows of h
    const float4* h4 = (const float4*)h;
    float4* hs4 = (float4*)h_sm;
    #pragma unroll
    for (int i = tid; i < 1024; i += 256) {          // 64 rows x 16 float4
        int node = node0 + (i >> 4);
        hs4[i] = (node < n_nodes) ? h4[(size_t)node * 16 + (i & 15)]
                                  : make_float4(0.f, 0.f, 0.f, 0.f);
    }
    __syncthreads();

    // Warp tiling: wid -> (wm in {0,1}: 32 rows, wn in {0..3}: 32 cols)
    const int wid = tid >> 5;
    const int wm  = wid & 1;
    const int wn  = wid >> 1;

    wmma::fragment<wmma::accumulator, 16, 16, 8, float> cfrag[2][2];
    #pragma unroll
    for (int tm = 0; tm < 2; ++tm)
        #pragma unroll
        for (int tn = 0; tn < 2; ++tn)
            wmma::fill_fragment(cfrag[tm][tn], 0.f);

    #pragma unroll
    for (int ks = 0; ks < 8; ++ks) {
        int k0 = ks * 8;
        wmma::fragment<wmma::matrix_a, 16, 16, 8, wmma::precision::tf32, wmma::row_major> afrag[2];
        wmma::fragment<wmma::matrix_b, 16, 16, 8, wmma::precision::tf32, wmma::row_major> bfrag[2];
        #pragma unroll
        for (int tm = 0; tm < 2; ++tm) {
            wmma::load_matrix_sync(afrag[tm], &h_sm[(wm * 32 + tm * 16) * 64 + k0], 64);
            #pragma unroll
            for (int t = 0; t < afrag[tm].num_elements; ++t)
                afrag[tm].x[t] = wmma::__float_to_tf32(afrag[tm].x[t]);
        }
        #pragma unroll
        for (int tn = 0; tn < 2; ++tn) {
            wmma::load_matrix_sync(bfrag[tn], &w_sm[k0 * 128 + wn * 32 + tn * 16], 128);
            #pragma unroll
            for (int t = 0; t < bfrag[tn].num_elements; ++t)
                bfrag[tn].x[t] = wmma::__float_to_tf32(bfrag[tn].x[t]);
        }
        #pragma unroll
        for (int tm = 0; tm < 2; ++tm)
            #pragma unroll
            for (int tn = 0; tn < 2; ++tn)
                wmma::mma_sync(cfrag[tm][tn], afrag[tm], bfrag[tn], cfrag[tm][tn]);
    }

    __syncthreads();   // everyone done reading h_sm/w_sm before C overwrite

    #pragma unroll
    for (int tm = 0; tm < 2; ++tm)
        #pragma unroll
        for (int tn = 0; tn < 2; ++tn)
            wmma::store_matrix_sync(&c_sm[(wm * 32 + tm * 16) * 128 + wn * 32 + tn * 16],
                                    cfrag[tm][tn], 128, wmma::mem_row_major);
    __syncthreads();

    // Write out: 64 nodes x 64 half2-pairs (32 A pairs + 32 B pairs per node)
    #pragma unroll
    for (int i = tid; i < 64 * 64; i += 256) {
        int nrow = i >> 6;
        int pair = i & 63;
        int node = node0 + nrow;
        if (node >= n_nodes) continue;
        if (pair < 32) {                       // A cols 2*pair, 2*pair+1
            int j = pair * 2;
            float x = c_sm[nrow * 128 + j]     + b1[j];
            float y = c_sm[nrow * 128 + j + 1] + b1[j + 1];
            *(half2*)&g_A[(size_t)node * HF + j] = __floats2half2_rn(x, y);
        } else {                               // B cols
            int j = (pair - 32) * 2;
            float x = c_sm[nrow * 128 + 64 + j];
            float y = c_sm[nrow * 128 + 64 + j + 1];
            *(half2*)&g_B[(size_t)node * HF + j] = __floats2half2_rn(x, y);
        }
    }
}

// ---------------- edge scoring: batched fp16 gather ----------------
// 8 lanes per edge; each warp handles 16 edges with all 8 gathers in flight.
__global__ __launch_bounds__(256)
void edge_kernel(const int* __restrict__ src,
                 const int* __restrict__ dst,
                 const float* __restrict__ W2,
                 const float* __restrict__ b2,
                 float* __restrict__ out, int n_edges)
{
    const int lane = threadIdx.x & 31;
    const int sub  = lane >> 3;   // 0..3
    const int l    = lane & 7;    // feature group (8 halves = 16 B)
    const int warp = blockIdx.x * 8 + (threadIdx.x >> 5);
    const int ebase = warp * 16 + sub;   // edges ebase + 4k, k=0..3

    int ec[4], s[4], d[4];
    #pragma unroll
    for (int k = 0; k < 4; ++k) {
        int e = ebase + k * 4;
        ec[k] = (e < n_edges) ? e : (n_edges - 1);
    }
    #pragma unroll
    for (int k = 0; k < 4; ++k) s[k] = src[ec[k]];
    #pragma unroll
    for (int k = 0; k < 4; ++k) d[k] = dst[ec[k]];

    const uint4* A4 = (const uint4*)g_A;   // 8 x uint4 per node row
    const uint4* B4 = (const uint4*)g_B;
    uint4 av[4], bv[4];
    #pragma unroll
    for (int k = 0; k < 4; ++k) av[k] = A4[(size_t)s[k] * 8 + l];
    #pragma unroll
    for (int k = 0; k < 4; ++k) bv[k] = B4[(size_t)d[k] * 8 + l];

    const float4* W24 = (const float4*)W2;
    float4 w0 = W24[l * 2];
    float4 w1 = W24[l * 2 + 1];
    float bias = b2[0];

    #pragma unroll
    for (int k = 0; k < 4; ++k) {
        const __half2* ah = (const __half2*)&av[k];
        const __half2* bh = (const __half2*)&bv[k];
        float2 a0 = __half22float2(ah[0]), b0 = __half22float2(bh[0]);
        float2 a1 = __half22float2(ah[1]), b1v = __half22float2(bh[1]);
        float2 a2 = __half22float2(ah[2]), b2v = __half22float2(bh[2]);
        float2 a3 = __half22float2(ah[3]), b3 = __half22float2(bh[3]);

        float acc = 0.f;
        acc = fmaf(fmaxf(a0.x + b0.x,  0.f), w0.x, acc);
        acc = fmaf(fmaxf(a0.y + b0.y,  0.f), w0.y, acc);
        acc = fmaf(fmaxf(a1.x + b1v.x, 0.f), w0.z, acc);
        acc = fmaf(fmaxf(a1.y + b1v.y, 0.f), w0.w, acc);
        acc = fmaf(fmaxf(a2.x + b2v.x, 0.f), w1.x, acc);
        acc = fmaf(fmaxf(a2.y + b2v.y, 0.f), w1.y, acc);
        acc = fmaf(fmaxf(a3.x + b3.x,  0.f), w1.z, acc);
        acc = fmaf(fmaxf(a3.y + b3.y,  0.f), w1.w, acc);

        // reduce within the 8-lane group (xor 4/2/1 never crosses groups)
        acc += __shfl_xor_sync(0xffffffffu, acc, 4);
        acc += __shfl_xor_sync(0xffffffffu, acc, 2);
        acc += __shfl_xor_sync(0xffffffffu, acc, 1);

        int e = ebase + k * 4;
        if (l == 0 && e < n_edges) out[e] = acc + bias;
    }
}

extern "C" void kernel_launch(void* const* d_in, const int* in_sizes, int n_in,
                              void* d_out, int out_size)
{
    const float* h   = (const float*)d_in[0];
    const int*   src = (const int*)d_in[1];
    const int*   dst = (const int*)d_in[2];
    const float* W1  = (const float*)d_in[3];
    const float* b1  = (const float*)d_in[4];
    const float* W2  = (const float*)d_in[5];
    const float* b2  = (const float*)d_in[6];
    float* out = (float*)d_out;

    int n_nodes = in_sizes[0] / HF;
    int n_edges = in_sizes[1];

    precompute_kernel<<<(n_nodes + 63) / 64, 256>>>(h, W1, b1, n_nodes);
    // 16 edges per warp, 8 warps per block -> 128 edges per block
    edge_kernel<<<(n_edges + 127) / 128, 256>>>(src, dst, W2, b2, out, n_edges);
}

// round 5
// speedup vs baseline: 2.4617x; 1.1153x over previous
#include <cuda_runtime.h>
#include <cuda_fp16.h>

#define HF 64
#define MAX_NODES 100000

// Scratch tables in fp16: A[n] = h[n]@W1[:64] + b1,  B[n] = h[n]@W1[64:]
__device__ __half g_A[MAX_NODES * HF];
__device__ __half g_B[MAX_NODES * HF];

// ---------------- precompute: per-node GEMM (scalar FMA, proven 29us) ----------------
// block: 256 threads, 64 nodes. thread: 8 nodes x 2 output feats (A and B).
__global__ __launch_bounds__(256)
void precompute_kernel(const float* __restrict__ h,
                       const float* __restrict__ W1,
                       const float* __restrict__ b1,
                       int n_nodes)
{
    __shared__ float h_sm[64 * HF];      // 16 KB
    __shared__ float w1s_sm[HF * HF];    // 16 KB
    __shared__ float w1d_sm[HF * HF];    // 16 KB

    const int tid   = threadIdx.x;
    const int node0 = blockIdx.x * 64;

    const float4* W14 = (const float4*)W1;
    float4* ws4 = (float4*)w1s_sm;
    float4* wd4 = (float4*)w1d_sm;
    #pragma unroll
    for (int i = tid; i < HF * HF / 4; i += 256) {
        ws4[i] = W14[i];
        wd4[i] = W14[i + HF * HF / 4];
    }
    const float4* h4 = (const float4*)h;
    float4* hs4 = (float4*)h_sm;
    #pragma unroll
    for (int i = tid; i < 64 * HF / 4; i += 256) {
        int node = node0 + (i >> 4);
        hs4[i] = (node < n_nodes) ? h4[(size_t)node * (HF / 4) + (i & 15)]
                                  : make_float4(0.f, 0.f, 0.f, 0.f);
    }
    __syncthreads();

    const int jg = tid & 31;
    const int j0 = jg * 2;
    const int ng = tid >> 5;
    const int nb = ng * 8;

    float aA[8][2], aB[8][2];
    #pragma unroll
    for (int ni = 0; ni < 8; ++ni) {
        aA[ni][0] = aA[ni][1] = 0.f;
        aB[ni][0] = aB[ni][1] = 0.f;
    }

    for (int k = 0; k < HF; k += 4) {
        float4 hv[8];
        #pragma unroll
        for (int ni = 0; ni < 8; ++ni)
            hv[ni] = *(const float4*)&h_sm[(nb + ni) * HF + k];
        #pragma unroll
        for (int kk = 0; kk < 4; ++kk) {
            float2 ws = *(const float2*)&w1s_sm[(k + kk) * HF + j0];
            float2 wd = *(const float2*)&w1d_sm[(k + kk) * HF + j0];
            #pragma unroll
            for (int ni = 0; ni < 8; ++ni) {
                float hvv = (kk == 0) ? hv[ni].x : (kk == 1) ? hv[ni].y
                          : (kk == 2) ? hv[ni].z : hv[ni].w;
                aA[ni][0] = fmaf(hvv, ws.x, aA[ni][0]);
                aA[ni][1] = fmaf(hvv, ws.y, aA[ni][1]);
                aB[ni][0] = fmaf(hvv, wd.x, aB[ni][0]);
                aB[ni][1] = fmaf(hvv, wd.y, aB[ni][1]);
            }
        }
    }

    float2 bb = *(const float2*)&b1[j0];
    #pragma unroll
    for (int ni = 0; ni < 8; ++ni) {
        int node = node0 + nb + ni;
        if (node < n_nodes) {
            *(half2*)&g_A[(size_t)node * HF + j0] =
                __floats2half2_rn(aA[ni][0] + bb.x, aA[ni][1] + bb.y);
            *(half2*)&g_B[(size_t)node * HF + j0] =
                __floats2half2_rn(aB[ni][0], aB[ni][1]);
        }
    }
}

// ---------------- edge scoring: deep-batched fp16 gather ----------------
// 8 lanes per edge; each warp handles 32 edges with 16 gathers in flight per thread.
__global__ __launch_bounds__(256, 2)
void edge_kernel(const int* __restrict__ src,
                 const int* __restrict__ dst,
                 const float* __restrict__ W2,
                 const float* __restrict__ b2,
                 float* __restrict__ out, int n_edges)
{
    const int lane = threadIdx.x & 31;
    const int sub  = lane >> 3;   // 0..3
    const int l    = lane & 7;    // feature group (8 halves = 16 B)
    const int warp = blockIdx.x * 8 + (threadIdx.x >> 5);
    const int ebase = warp * 32 + sub;   // edges ebase + 4k, k=0..7

    int ec[8];
    #pragma unroll
    for (int k = 0; k < 8; ++k) {
        int e = ebase + k * 4;
        ec[k] = (e < n_edges) ? e : (n_edges - 1);
    }
    int s[8], d[8];
    #pragma unroll
    for (int k = 0; k < 8; ++k) s[k] = src[ec[k]];
    #pragma unroll
    for (int k = 0; k < 8; ++k) d[k] = dst[ec[k]];

    const uint4* A4 = (const uint4*)g_A;   // 8 x uint4 per node row
    const uint4* B4 = (const uint4*)g_B;
    uint4 av[8], bv[8];
    #pragma unroll
    for (int k = 0; k < 8; ++k) av[k] = A4[(size_t)s[k] * 8 + l];
    #pragma unroll
    for (int k = 0; k < 8; ++k) bv[k] = B4[(size_t)d[k] * 8 + l];

    const float4* W24 = (const float4*)W2;
    float4 w0 = W24[l * 2];
    float4 w1 = W24[l * 2 + 1];
    float bias = b2[0];

    #pragma unroll
    for (int k = 0; k < 8; ++k) {
        const __half2* ah = (const __half2*)&av[k];
        const __half2* bh = (const __half2*)&bv[k];
        float2 a0 = __half22float2(ah[0]), b0 = __half22float2(bh[0]);
        float2 a1 = __half22float2(ah[1]), b1v = __half22float2(bh[1]);
        float2 a2 = __half22float2(ah[2]), b2v = __half22float2(bh[2]);
        float2 a3 = __half22float2(ah[3]), b3 = __half22float2(bh[3]);

        float acc = 0.f;
        acc = fmaf(fmaxf(a0.x + b0.x,  0.f), w0.x, acc);
        acc = fmaf(fmaxf(a0.y + b0.y,  0.f), w0.y, acc);
        acc = fmaf(fmaxf(a1.x + b1v.x, 0.f), w0.z, acc);
        acc = fmaf(fmaxf(a1.y + b1v.y, 0.f), w0.w, acc);
        acc = fmaf(fmaxf(a2.x + b2v.x, 0.f), w1.x, acc);
        acc = fmaf(fmaxf(a2.y + b2v.y, 0.f), w1.y, acc);
        acc = fmaf(fmaxf(a3.x + b3.x,  0.f), w1.z, acc);
        acc = fmaf(fmaxf(a3.y + b3.y,  0.f), w1.w, acc);

        acc += __shfl_xor_sync(0xffffffffu, acc, 4);
        acc += __shfl_xor_sync(0xffffffffu, acc, 2);
        acc += __shfl_xor_sync(0xffffffffu, acc, 1);

        int e = ebase + k * 4;
        if (l == 0 && e < n_edges) out[e] = acc + bias;
    }
}

extern "C" void kernel_launch(void* const* d_in, const int* in_sizes, int n_in,
                              void* d_out, int out_size)
{
    const float* h   = (const float*)d_in[0];
    const int*   src = (const int*)d_in[1];
    const int*   dst = (const int*)d_in[2];
    const float* W1  = (const float*)d_in[3];
    const float* b1  = (const float*)d_in[4];
    const float* W2  = (const float*)d_in[5];
    const float* b2  = (const float*)d_in[6];
    float* out = (float*)d_out;

    int n_nodes = in_sizes[0] / HF;
    int n_edges = in_sizes[1];

    precompute_kernel<<<(n_nodes + 63) / 64, 256>>>(h, W1, b1, n_nodes);
    // 32 edges per warp, 8 warps per block -> 256 edges per block
    edge_kernel<<<(n_edges + 255) / 256, 256>>>(src, dst, W2, b2, out, n_edges);
}

// round 7
// speedup vs baseline: 2.7323x; 1.1099x over previous
#include <cuda_runtime.h>
#include <cuda_fp16.h>

#define HF 64
#define MAX_NODES 100000

// Scratch tables in fp16: A[n] = h[n]@W1[:64] + b1,  B[n] = h[n]@W1[64:]
__device__ __half g_A[MAX_NODES * HF];
__device__ __half g_B[MAX_NODES * HF];

// Packed fp32x2 FMA (Blackwell): acc = a * b + acc, per 32-bit lane.
__device__ __forceinline__ void ffma2(unsigned long long& acc,
                                      unsigned long long a,
                                      unsigned long long b) {
    asm("fma.rn.f32x2 %0, %1, %2, %0;" : "+l"(acc) : "l"(a), "l"(b));
}
__device__ __forceinline__ unsigned long long splat2(float v) {
    unsigned long long r;
    asm("mov.b64 %0, {%1, %1};" : "=l"(r) : "f"(v));
    return r;
}

// ---------------- precompute: per-node GEMM with f32x2 packed FMA ----------------
// block: 256 threads, 64 nodes. thread: 8 nodes x 2 output feats (A and B),
// each (j0,j0+1) pair held as one packed f32x2 accumulator.
__global__ __launch_bounds__(256)
void precompute_kernel(const float* __restrict__ h,
                       const float* __restrict__ W1,
                       const float* __restrict__ b1,
                       int n_nodes)
{
    __shared__ float h_sm[64 * HF];      // 16 KB
    __shared__ float w1s_sm[HF * HF];    // 16 KB
    __shared__ float w1d_sm[HF * HF];    // 16 KB

    const int tid   = threadIdx.x;
    const int node0 = blockIdx.x * 64;

    const float4* W14 = (const float4*)W1;
    float4* ws4 = (float4*)w1s_sm;
    float4* wd4 = (float4*)w1d_sm;
    #pragma unroll
    for (int i = tid; i < HF * HF / 4; i += 256) {
        ws4[i] = W14[i];
        wd4[i] = W14[i + HF * HF / 4];
    }
    const float4* h4 = (const float4*)h;
    float4* hs4 = (float4*)h_sm;
    #pragma unroll
    for (int i = tid; i < 64 * HF / 4; i += 256) {
        int node = node0 + (i >> 4);
        hs4[i] = (node < n_nodes) ? h4[(size_t)node * (HF / 4) + (i & 15)]
                                  : make_float4(0.f, 0.f, 0.f, 0.f);
    }
    __syncthreads();

    const int jg = tid & 31;
    const int j0 = jg * 2;                 // feature pair (j0, j0+1)
    const int ng = tid >> 5;
    const int nb = ng * 8;

    unsigned long long accA[8], accB[8];   // packed f32x2 accumulators
    #pragma unroll
    for (int ni = 0; ni < 8; ++ni) { accA[ni] = 0ull; accB[ni] = 0ull; }

    for (int k = 0; k < HF; k += 4) {
        float4 hv[8];
        #pragma unroll
        for (int ni = 0; ni < 8; ++ni)
            hv[ni] = *(const float4*)&h_sm[(nb + ni) * HF + k];
        #pragma unroll
        for (int kk = 0; kk < 4; ++kk) {
            unsigned long long wsp = *(const unsigned long long*)&w1s_sm[(k + kk) * HF + j0];
            unsigned long long wdp = *(const unsigned long long*)&w1d_sm[(k + kk) * HF + j0];
            #pragma unroll
            for (int ni = 0; ni < 8; ++ni) {
                float hvv = (kk == 0) ? hv[ni].x : (kk == 1) ? hv[ni].y
                          : (kk == 2) ? hv[ni].z : hv[ni].w;
                unsigned long long hp = splat2(hvv);
                ffma2(accA[ni], hp, wsp);
                ffma2(accB[ni], hp, wdp);
            }
        }
    }

    float2 bb = *(const float2*)&b1[j0];
    #pragma unroll
    for (int ni = 0; ni < 8; ++ni) {
        int node = node0 + nb + ni;
        if (node < n_nodes) {
            float2 ra = *(float2*)&accA[ni];
            float2 rb = *(float2*)&accB[ni];
            *(half2*)&g_A[(size_t)node * HF + j0] =
                __floats2half2_rn(ra.x + bb.x, ra.y + bb.y);
            *(half2*)&g_B[(size_t)node * HF + j0] =
                __floats2half2_rn(rb.x, rb.y);
        }
    }
}

// ---------------- edge scoring: batched fp16 gather (R4 proven config) ----------------
// 8 lanes per edge; each warp handles 16 edges with 8 gathers in flight.
__global__ __launch_bounds__(256)
void edge_kernel(const int* __restrict__ src,
                 const int* __restrict__ dst,
                 const float* __restrict__ W2,
                 const float* __restrict__ b2,
                 float* __restrict__ out, int n_edges)
{
    const int lane = threadIdx.x & 31;
    const int sub  = lane >> 3;   // 0..3
    const int l    = lane & 7;    // feature group (8 halves = 16 B)
    const int warp = blockIdx.x * 8 + (threadIdx.x >> 5);
    const int ebase = warp * 16 + sub;   // edges ebase + 4k, k=0..3

    int ec[4], s[4], d[4];
    #pragma unroll
    for (int k = 0; k < 4; ++k) {
        int e = ebase + k * 4;
        ec[k] = (e < n_edges) ? e : (n_edges - 1);
    }
    #pragma unroll
    for (int k = 0; k < 4; ++k) s[k] = src[ec[k]];
    #pragma unroll
    for (int k = 0; k < 4; ++k) d[k] = dst[ec[k]];

    const uint4* A4 = (const uint4*)g_A;   // 8 x uint4 per node row
    const uint4* B4 = (const uint4*)g_B;
    uint4 av[4], bv[4];
    #pragma unroll
    for (int k = 0; k < 4; ++k) av[k] = A4[(size_t)s[k] * 8 + l];
    #pragma unroll
    for (int k = 0; k < 4; ++k) bv[k] = B4[(size_t)d[k] * 8 + l];

    const float4* W24 = (const float4*)W2;
    float4 w0 = W24[l * 2];
    float4 w1 = W24[l * 2 + 1];
    float bias = b2[0];

    #pragma unroll
    for (int k = 0; k < 4; ++k) {
        const __half2* ah = (const __half2*)&av[k];
        const __half2* bh = (const __half2*)&bv[k];
        float2 a0 = __half22float2(ah[0]), b0 = __half22float2(bh[0]);
        float2 a1 = __half22float2(ah[1]), b1v = __half22float2(bh[1]);
        float2 a2 = __half22float2(ah[2]), b2v = __half22float2(bh[2]);
        float2 a3 = __half22float2(ah[3]), b3 = __half22float2(bh[3]);

        float acc = 0.f;
        acc = fmaf(fmaxf(a0.x + b0.x,  0.f), w0.x, acc);
        acc = fmaf(fmaxf(a0.y + b0.y,  0.f), w0.y, acc);
        acc = fmaf(fmaxf(a1.x + b1v.x, 0.f), w0.z, acc);
        acc = fmaf(fmaxf(a1.y + b1v.y, 0.f), w0.w, acc);
        acc = fmaf(fmaxf(a2.x + b2v.x, 0.f), w1.x, acc);
        acc = fmaf(fmaxf(a2.y + b2v.y, 0.f), w1.y, acc);
        acc = fmaf(fmaxf(a3.x + b3.x,  0.f), w1.z, acc);
        acc = fmaf(fmaxf(a3.y + b3.y,  0.f), w1.w, acc);

        acc += __shfl_xor_sync(0xffffffffu, acc, 4);
        acc += __shfl_xor_sync(0xffffffffu, acc, 2);
        acc += __shfl_xor_sync(0xffffffffu, acc, 1);

        int e = ebase + k * 4;
        if (l == 0 && e < n_edges) out[e] = acc + bias;
    }
}

extern "C" void kernel_launch(void* const* d_in, const int* in_sizes, int n_in,
                              void* d_out, int out_size)
{
    const float* h   = (const float*)d_in[0];
    const int*   src = (const int*)d_in[1];
    const int*   dst = (const int*)d_in[2];
    const float* W1  = (const float*)d_in[3];
    const float* b1  = (const float*)d_in[4];
    const float* W2  = (const float*)d_in[5];
    const float* b2  = (const float*)d_in[6];
    float* out = (float*)d_out;

    int n_nodes = in_sizes[0] / HF;
    int n_edges = in_sizes[1];

    precompute_kernel<<<(n_nodes + 63) / 64, 256>>>(h, W1, b1, n_nodes);
    // 16 edges per warp, 8 warps per block -> 128 edges per block
    edge_kernel<<<(n_edges + 127) / 128, 256>>>(src, dst, W2, b2, out, n_edges);
}

// round 10
// speedup vs baseline: 2.8011x; 1.0252x over previous
#include <cuda_runtime.h>
#include <cuda_fp16.h>

#define HF 64
#define MAX_NODES 100000

// Scratch tables in fp16: A[n] = h[n]@W1[:64] + b1,  B[n] = h[n]@W1[64:]
__device__ __half g_A[MAX_NODES * HF];
__device__ __half g_B[MAX_NODES * HF];

// Packed fp32x2 FMA (Blackwell): acc = a * b + acc, per 32-bit lane.
__device__ __forceinline__ void ffma2(unsigned long long& acc,
                                      unsigned long long a,
                                      unsigned long long b) {
    asm("fma.rn.f32x2 %0, %1, %2, %0;" : "+l"(acc) : "l"(a), "l"(b));
}
__device__ __forceinline__ unsigned long long splat2(float v) {
    unsigned long long r;
    asm("mov.b64 %0, {%1, %1};" : "=l"(r) : "f"(v));
    return r;
}
__device__ __forceinline__ unsigned long long pack2(float lo, float hi) {
    unsigned long long r;
    asm("mov.b64 %0, {%1, %2};" : "=l"(r) : "f"(lo), "f"(hi));
    return r;
}

// ---------------- precompute: per-node GEMM with f32x2 packed FMA ----------------
__global__ __launch_bounds__(256)
void precompute_kernel(const float* __restrict__ h,
                       const float* __restrict__ W1,
                       const float* __restrict__ b1,
                       int n_nodes)
{
    __shared__ float h_sm[64 * HF];      // 16 KB
    __shared__ float w1s_sm[HF * HF];    // 16 KB
    __shared__ float w1d_sm[HF * HF];    // 16 KB

    const int tid   = threadIdx.x;
    const int node0 = blockIdx.x * 64;

    const float4* W14 = (const float4*)W1;
    float4* ws4 = (float4*)w1s_sm;
    float4* wd4 = (float4*)w1d_sm;
    #pragma unroll
    for (int i = tid; i < HF * HF / 4; i += 256) {
        ws4[i] = W14[i];
        wd4[i] = W14[i + HF * HF / 4];
    }
    const float4* h4 = (const float4*)h;
    float4* hs4 = (float4*)h_sm;
    #pragma unroll
    for (int i = tid; i < 64 * HF / 4; i += 256) {
        int node = node0 + (i >> 4);
        hs4[i] = (node < n_nodes) ? h4[(size_t)node * (HF / 4) + (i & 15)]
                                  : make_float4(0.f, 0.f, 0.f, 0.f);
    }
    __syncthreads();

    const int jg = tid & 31;
    const int j0 = jg * 2;                 // feature pair (j0, j0+1)
    const int ng = tid >> 5;
    const int nb = ng * 8;

    unsigned long long accA[8], accB[8];   // packed f32x2 accumulators
    #pragma unroll
    for (int ni = 0; ni < 8; ++ni) { accA[ni] = 0ull; accB[ni] = 0ull; }

    for (int k = 0; k < HF; k += 4) {
        float4 hv[8];
        #pragma unroll
        for (int ni = 0; ni < 8; ++ni)
            hv[ni] = *(const float4*)&h_sm[(nb + ni) * HF + k];
        #pragma unroll
        for (int kk = 0; kk < 4; ++kk) {
            unsigned long long wsp = *(const unsigned long long*)&w1s_sm[(k + kk) * HF + j0];
            unsigned long long wdp = *(const unsigned long long*)&w1d_sm[(k + kk) * HF + j0];
            #pragma unroll
            for (int ni = 0; ni < 8; ++ni) {
                float hvv = (kk == 0) ? hv[ni].x : (kk == 1) ? hv[ni].y
                          : (kk == 2) ? hv[ni].z : hv[ni].w;
                unsigned long long hp = splat2(hvv);
                ffma2(accA[ni], hp, wsp);
                ffma2(accB[ni], hp, wdp);
            }
        }
    }

    float2 bb = *(const float2*)&b1[j0];
    #pragma unroll
    for (int ni = 0; ni < 8; ++ni) {
        int node = node0 + nb + ni;
        if (node < n_nodes) {
            float2 ra = *(float2*)&accA[ni];
            float2 rb = *(float2*)&accB[ni];
            *(half2*)&g_A[(size_t)node * HF + j0] =
                __floats2half2_rn(ra.x + bb.x, ra.y + bb.y);
            *(half2*)&g_B[(size_t)node * HF + j0] =
                __floats2half2_rn(rb.x, rb.y);
        }
    }
}

// ---------------- edge scoring: batched fp16 gather, packed math ----------------
// 8 lanes per edge; each warp handles 16 edges with 8 gathers in flight.
// Math: HADD2+HMAX2 (half2 add+relu), CVT, then fma.rn.f32x2 dot.
__global__ __launch_bounds__(256)
void edge_kernel(const int* __restrict__ src,
                 const int* __restrict__ dst,
                 const float* __restrict__ W2,
                 const float* __restrict__ b2,
                 float* __restrict__ out, int n_edges)
{
    const int lane = threadIdx.x & 31;
    const int sub  = lane >> 3;   // 0..3
    const int l    = lane & 7;    // feature group (8 halves = 16 B)
    const int warp = blockIdx.x * 8 + (threadIdx.x >> 5);
    const int ebase = warp * 16 + sub;   // edges ebase + 4k, k=0..3

    int ec[4], s[4], d[4];
    #pragma unroll
    for (int k = 0; k < 4; ++k) {
        int e = ebase + k * 4;
        ec[k] = (e < n_edges) ? e : (n_edges - 1);
    }
    #pragma unroll
    for (int k = 0; k < 4; ++k) s[k] = src[ec[k]];
    #pragma unroll
    for (int k = 0; k < 4; ++k) d[k] = dst[ec[k]];

    const uint4* A4 = (const uint4*)g_A;   // 8 x uint4 per node row
    const uint4* B4 = (const uint4*)g_B;
    uint4 av[4], bv[4];
    #pragma unroll
    for (int k = 0; k < 4; ++k) av[k] = A4[(size_t)s[k] * 8 + l];
    #pragma unroll
    for (int k = 0; k < 4; ++k) bv[k] = B4[(size_t)d[k] * 8 + l];

    // w2 for this lane's 8 features, pre-packed as 4 x f32x2
    const float4* W24 = (const float4*)W2;
    float4 w0 = W24[l * 2];
    float4 w1 = W24[l * 2 + 1];
    unsigned long long wp[4];
    wp[0] = pack2(w0.x, w0.y);
    wp[1] = pack2(w0.z, w0.w);
    wp[2] = pack2(w1.x, w1.y);
    wp[3] = pack2(w1.z, w1.w);
    float bias = b2[0];

    const __half2 hz = __float2half2_rn(0.f);

    #pragma unroll
    for (int k = 0; k < 4; ++k) {
        const __half2* ah = (const __half2*)&av[k];
        const __half2* bh = (const __half2*)&bv[k];

        unsigned long long acc2 = 0ull;
        #pragma unroll
        for (int p = 0; p < 4; ++p) {
            __half2 v = __hmax2(__hadd2(ah[p], bh[p]), hz);   // add + relu in fp16
            float2 f = __half22float2(v);
            ffma2(acc2, pack2(f.x, f.y), wp[p]);
        }

        float2 r = *(float2*)&acc2;
        float acc = r.x + r.y;

        acc += __shfl_xor_sync(0xffffffffu, acc, 4);
        acc += __shfl_xor_sync(0xffffffffu, acc, 2);
        acc += __shfl_xor_sync(0xffffffffu, acc, 1);

        int e = ebase + k * 4;
        if (l == 0 && e < n_edges) out[e] = acc + bias;
    }
}

extern "C" void kernel_launch(void* const* d_in, const int* in_sizes, int n_in,
                              void* d_out, int out_size)
{
    const float* h   = (const float*)d_in[0];
    const int*   src = (const int*)d_in[1];
    const int*   dst = (const int*)d_in[2];
    const float* W1  = (const float*)d_in[3];
    const float* b1  = (const float*)d_in[4];
    const float* W2  = (const float*)d_in[5];
    const float* b2  = (const float*)d_in[6];
    float* out = (float*)d_out;

    int n_nodes = in_sizes[0] / HF;
    int n_edges = in_sizes[1];

    precompute_kernel<<<(n_nodes + 63) / 64, 256>>>(h, W1, b1, n_nodes);
    // 16 edges per warp, 8 warps per block -> 128 edges per block
    edge_kernel<<<(n_edges + 127) / 128, 256>>>(src, dst, W2, b2, out, n_edges);
}

// round 12
// speedup vs baseline: 3.4926x; 1.2468x over previous
#include <cuda_runtime.h>
#include <cuda_fp16.h>
#include <cstdint>

#define HF 64
#define MAX_NODES 100000

// Scratch tables in fp16: A[n] = h[n]@W1[:64] + b1,  B[n] = h[n]@W1[64:]
__device__ __half g_A[MAX_NODES * HF];
__device__ __half g_B[MAX_NODES * HF];

// ---------------- PTX helpers ----------------
__device__ __forceinline__ uint32_t smem_u32(const void* p) {
    uint32_t a;
    asm("{ .reg .u64 t; cvta.to.shared.u64 t, %1; cvt.u32.u64 %0, t; }"
        : "=r"(a) : "l"(p));
    return a;
}
__device__ __forceinline__ void ldsm_x4(uint32_t& r0, uint32_t& r1,
                                        uint32_t& r2, uint32_t& r3, uint32_t addr) {
    asm volatile("ldmatrix.sync.aligned.m8n8.x4.shared.b16 {%0,%1,%2,%3}, [%4];"
                 : "=r"(r0), "=r"(r1), "=r"(r2), "=r"(r3) : "r"(addr));
}
__device__ __forceinline__ void ldsm_x2(uint32_t& r0, uint32_t& r1, uint32_t addr) {
    asm volatile("ldmatrix.sync.aligned.m8n8.x2.shared.b16 {%0,%1}, [%2];"
                 : "=r"(r0), "=r"(r1) : "r"(addr));
}
__device__ __forceinline__ void mma16816(float& d0, float& d1, float& d2, float& d3,
                                         uint32_t a0, uint32_t a1, uint32_t a2, uint32_t a3,
                                         uint32_t b0, uint32_t b1) {
    asm volatile("mma.sync.aligned.m16n8k16.row.col.f32.f16.f16.f32 "
                 "{%0,%1,%2,%3}, {%4,%5,%6,%7}, {%8,%9}, {%0,%1,%2,%3};"
                 : "+f"(d0), "+f"(d1), "+f"(d2), "+f"(d3)
                 : "r"(a0), "r"(a1), "r"(a2), "r"(a3), "r"(b0), "r"(b1));
}
__device__ __forceinline__ void ffma2(unsigned long long& acc,
                                      unsigned long long a,
                                      unsigned long long b) {
    asm("fma.rn.f32x2 %0, %1, %2, %0;" : "+l"(acc) : "l"(a), "l"(b));
}
__device__ __forceinline__ unsigned long long pack2(float lo, float hi) {
    unsigned long long r;
    asm("mov.b64 %0, {%1, %2};" : "=l"(r) : "f"(lo), "f"(hi));
    return r;
}

// ---------------- precompute: fp16 mma.sync, register-direct epilogue ----------------
// Per block: 64 nodes (M) x 128 outputs (N=[A|B]), K=64.
// 8 warps = 4 m-tiles (16 rows) x 2 n-strips (64 cols); 8 n-tiles x 4 k-steps per warp.
#define HSTR 72   // fp16 smem row stride (bank-rotation padding for ldmatrix)

__global__ __launch_bounds__(256)
void precompute_kernel(const float* __restrict__ h,
                       const float* __restrict__ W1,
                       const float* __restrict__ b1,
                       int n_nodes)
{
    __shared__ __half hh[64 * HSTR];     // h tile, 64x64 used
    __shared__ __half ww[128 * HSTR];    // W'^T : ww[j][k] = W'(k,j)

    const int tid   = threadIdx.x;
    const int node0 = blockIdx.x * 64;

    // hh: convert 64 node rows fp32 -> fp16
    const float4* h4 = (const float4*)h;
    #pragma unroll
    for (int i = tid; i < 1024; i += 256) {          // 64 rows x 16 float4
        int row = i >> 4, c4 = (i & 15) * 4;
        int node = node0 + row;
        float4 v = (node < n_nodes) ? h4[(size_t)node * 16 + (i & 15)]
                                    : make_float4(0.f, 0.f, 0.f, 0.f);
        *(half2*)&hh[row * HSTR + c4]     = __floats2half2_rn(v.x, v.y);
        *(half2*)&hh[row * HSTR + c4 + 2] = __floats2half2_rn(v.z, v.w);
    }
    // ww[j][k]: j<64 -> W1[k*64+j] (src half), j>=64 -> W1[(64+k)*64 + j-64] (dst half)
    #pragma unroll
    for (int i = tid; i < 8192; i += 256) {
        int j = i & 127, k = i >> 7;
        float v = (j < 64) ? W1[k * 64 + j] : W1[(64 + k) * 64 + (j - 64)];
        ww[j * HSTR + k] = __float2half_rn(v);
    }
    __syncthreads();

    const uint32_t hh_base = smem_u32(hh);
    const uint32_t ww_base = smem_u32(ww);
    const int w    = tid >> 5;
    const int lane = tid & 31;
    const int m0    = (w & 3) * 16;
    const int nbase = (w >> 2) * 64;

    // A fragments for all 4 k-steps (k16 each)
    uint32_t A[4][4];
    {
        int row = m0 + (lane & 15);
        int kh  = (lane >> 4) * 8;
        #pragma unroll
        for (int ks = 0; ks < 4; ++ks) {
            uint32_t addr = hh_base + (uint32_t)(row * HSTR + ks * 16 + kh) * 2u;
            ldsm_x4(A[ks][0], A[ks][1], A[ks][2], A[ks][3], addr);
        }
    }

    const int brow = (lane & 7);
    const int bkh  = ((lane >> 3) & 1) * 8;
    const int r    = lane >> 2;
    const int cpos = (lane & 3) * 2;

    #pragma unroll
    for (int nt = 0; nt < 8; ++nt) {
        int n0 = nbase + nt * 8;
        float c0 = 0.f, c1 = 0.f, c2 = 0.f, c3 = 0.f;
        #pragma unroll
        for (int ks = 0; ks < 4; ++ks) {
            uint32_t bb0, bb1;
            uint32_t addr = ww_base + (uint32_t)((n0 + brow) * HSTR + ks * 16 + bkh) * 2u;
            ldsm_x2(bb0, bb1, addr);
            mma16816(c0, c1, c2, c3, A[ks][0], A[ks][1], A[ks][2], A[ks][3], bb0, bb1);
        }
        int col   = n0 + cpos;
        int nodeA = node0 + m0 + r;
        int nodeB = nodeA + 8;
        if (col < 64) {
            float2 bpair = *(const float2*)&b1[col];
            if (nodeA < n_nodes)
                *(half2*)&g_A[(size_t)nodeA * HF + col] = __floats2half2_rn(c0 + bpair.x, c1 + bpair.y);
            if (nodeB < n_nodes)
                *(half2*)&g_A[(size_t)nodeB * HF + col] = __floats2half2_rn(c2 + bpair.x, c3 + bpair.y);
        } else {
            int cb = col - 64;
            if (nodeA < n_nodes)
                *(half2*)&g_B[(size_t)nodeA * HF + cb] = __floats2half2_rn(c0, c1);
            if (nodeB < n_nodes)
                *(half2*)&g_B[(size_t)nodeB * HF + cb] = __floats2half2_rn(c2, c3);
        }
    }
}

// ---------------- edge scoring: batched fp16 gather, packed math (R10 proven) ----------------
__global__ __launch_bounds__(256)
void edge_kernel(const int* __restrict__ src,
                 const int* __restrict__ dst,
                 const float* __restrict__ W2,
                 const float* __restrict__ b2,
                 float* __restrict__ out, int n_edges)
{
    const int lane = threadIdx.x & 31;
    const int sub  = lane >> 3;   // 0..3
    const int l    = lane & 7;    // feature group (8 halves = 16 B)
    const int warp = blockIdx.x * 8 + (threadIdx.x >> 5);
    const int ebase = warp * 16 + sub;   // edges ebase + 4k, k=0..3

    int ec[4], s[4], d[4];
    #pragma unroll
    for (int k = 0; k < 4; ++k) {
        int e = ebase + k * 4;
        ec[k] = (e < n_edges) ? e : (n_edges - 1);
    }
    #pragma unroll
    for (int k = 0; k < 4; ++k) s[k] = src[ec[k]];
    #pragma unroll
    for (int k = 0; k < 4; ++k) d[k] = dst[ec[k]];

    const uint4* A4 = (const uint4*)g_A;   // 8 x uint4 per node row
    const uint4* B4 = (const uint4*)g_B;
    uint4 av[4], bv[4];
    #pragma unroll
    for (int k = 0; k < 4; ++k) av[k] = A4[(size_t)s[k] * 8 + l];
    #pragma unroll
    for (int k = 0; k < 4; ++k) bv[k] = B4[(size_t)d[k] * 8 + l];

    const float4* W24 = (const float4*)W2;
    float4 w0 = W24[l * 2];
    float4 w1 = W24[l * 2 + 1];
    unsigned long long wp0 = pack2(w0.x, w0.y);
    unsigned long long wp1 = pack2(w0.z, w0.w);
    unsigned long long wp2 = pack2(w1.x, w1.y);
    unsigned long long wp3 = pack2(w1.z, w1.w);
    float bias = b2[0];

    const __half2 hz = __float2half2_rn(0.f);

    #pragma unroll
    for (int k = 0; k < 4; ++k) {
        const __half2* ah = (const __half2*)&av[k];
        const __half2* bh = (const __half2*)&bv[k];

        unsigned long long acc2 = 0ull;
        {
            __half2 v0 = __hmax2(__hadd2(ah[0], bh[0]), hz);
            float2 f0 = __half22float2(v0);
            ffma2(acc2, pack2(f0.x, f0.y), wp0);
            __half2 v1 = __hmax2(__hadd2(ah[1], bh[1]), hz);
            float2 f1 = __half22float2(v1);
            ffma2(acc2, pack2(f1.x, f1.y), wp1);
            __half2 v2 = __hmax2(__hadd2(ah[2], bh[2]), hz);
            float2 f2 = __half22float2(v2);
            ffma2(acc2, pack2(f2.x, f2.y), wp2);
            __half2 v3 = __hmax2(__hadd2(ah[3], bh[3]), hz);
            float2 f3 = __half22float2(v3);
            ffma2(acc2, pack2(f3.x, f3.y), wp3);
        }

        float2 rr = *(float2*)&acc2;
        float acc = rr.x + rr.y;

        acc += __shfl_xor_sync(0xffffffffu, acc, 4);
        acc += __shfl_xor_sync(0xffffffffu, acc, 2);
        acc += __shfl_xor_sync(0xffffffffu, acc, 1);

        int e = ebase + k * 4;
        if (l == 0 && e < n_edges) out[e] = acc + bias;
    }
}

extern "C" void kernel_launch(void* const* d_in, const int* in_sizes, int n_in,
                              void* d_out, int out_size)
{
    const float* h   = (const float*)d_in[0];
    const int*   src = (const int*)d_in[1];
    const int*   dst = (const int*)d_in[2];
    const float* W1  = (const float*)d_in[3];
    const float* b1  = (const float*)d_in[4];
    const float* W2  = (const float*)d_in[5];
    const float* b2  = (const float*)d_in[6];
    float* out = (float*)d_out;

    int n_nodes = in_sizes[0] / HF;
    int n_edges = in_sizes[1];

    precompute_kernel<<<(n_nodes + 63) / 64, 256>>>(h, W1, b1, n_nodes);
    // 16 edges per warp, 8 warps per block -> 128 edges per block
    edge_kernel<<<(n_edges + 127) / 128, 256>>>(src, dst, W2, b2, out, n_edges);
}